// round 1
// baseline (speedup 1.0000x reference)
#include <cuda_runtime.h>

#define B_ 16
#define T_ 2048
#define D_ 256
#define C_ 8
#define TCHUNK 64
#define NWARPS 8
#define ROWS_PER_WARP (TCHUNK / NWARPS)   // 8
#define NCHUNKS (T_ / TCHUNK)             // 32
#define NBLOCKS (B_ * NCHUNKS)            // 512

__global__ void lde_zero_kernel(float* __restrict__ out, int n) {
    int i = blockIdx.x * blockDim.x + threadIdx.x;
    if (i < n) out[i] = 0.0f;
}

__global__ __launch_bounds__(256) void lde_main_kernel(
    const float* __restrict__ x,        // (B,T,D)
    const float* __restrict__ centers,  // (C,D)
    const float* __restrict__ scale,    // (C,)
    float* __restrict__ out)            // (B, C*D)
{
    const int b     = blockIdx.x / NCHUNKS;
    const int chunk = blockIdx.x % NCHUNKS;
    const int tid   = threadIdx.x;
    const int warp  = tid >> 5;
    const int lane  = tid & 31;

    // ---- centers in registers: lane l owns dims {l, l+32, ..., l+224} ----
    float creg[C_][8];
#pragma unroll
    for (int c = 0; c < C_; c++)
#pragma unroll
        for (int k = 0; k < 8; k++)
            creg[c][k] = centers[c * D_ + lane + 32 * k];

    // ---- ||c||^2 per cluster (one-time warp reduction) ----
    float csq[C_];
#pragma unroll
    for (int c = 0; c < C_; c++) {
        float s = 0.0f;
#pragma unroll
        for (int k = 0; k < 8; k++) s = fmaf(creg[c][k], creg[c][k], s);
#pragma unroll
        for (int off = 16; off > 0; off >>= 1)
            s += __shfl_xor_sync(0xffffffffu, s, off);
        csq[c] = s;
    }

    float scl[C_];
#pragma unroll
    for (int c = 0; c < C_; c++) scl[c] = scale[c];

    float acc[C_][8];
    float asum[C_];
#pragma unroll
    for (int c = 0; c < C_; c++) {
        asum[c] = 0.0f;
#pragma unroll
        for (int k = 0; k < 8; k++) acc[c][k] = 0.0f;
    }

    const int t0 = chunk * TCHUNK + warp * ROWS_PER_WARP;
    const float* xb = x + (size_t)b * T_ * D_;

    for (int r = 0; r < ROWS_PER_WARP; r++) {
        const float* xr = xb + (size_t)(t0 + r) * D_;

        float xv[8];
#pragma unroll
        for (int k = 0; k < 8; k++) xv[k] = xr[lane + 32 * k];

        // partial dots with each center + partial ||x||^2
        float red[C_ + 1];
#pragma unroll
        for (int c = 0; c < C_; c++) {
            float d = 0.0f;
#pragma unroll
            for (int k = 0; k < 8; k++) d = fmaf(xv[k], creg[c][k], d);
            red[c] = d;
        }
        {
            float xs = 0.0f;
#pragma unroll
            for (int k = 0; k < 8; k++) xs = fmaf(xv[k], xv[k], xs);
            red[C_] = xs;
        }

        // butterfly reduce all 9 values -> every lane has full sums
#pragma unroll
        for (int off = 16; off > 0; off >>= 1) {
#pragma unroll
            for (int j = 0; j < C_ + 1; j++)
                red[j] += __shfl_xor_sync(0xffffffffu, red[j], off);
        }

        // logits: -scale_c * (||x||^2 - 2 x.c + ||c||^2)
        float lg[C_];
        float m = -1e30f;
#pragma unroll
        for (int c = 0; c < C_; c++) {
            lg[c] = -scl[c] * (red[C_] - 2.0f * red[c] + csq[c]);
            m = fmaxf(m, lg[c]);
        }
        float e[C_];
        float s = 0.0f;
#pragma unroll
        for (int c = 0; c < C_; c++) {
            e[c] = __expf(lg[c] - m);
            s += e[c];
        }
        const float inv = 1.0f / s;
#pragma unroll
        for (int c = 0; c < C_; c++) {
            const float a = e[c] * inv;
            asum[c] += a;
#pragma unroll
            for (int k = 0; k < 8; k++) acc[c][k] = fmaf(a, xv[k], acc[c][k]);
        }
    }

    // ---- block reduction through shared memory ----
    __shared__ float tile[C_ * D_];   // 8 KB
    __shared__ float asum_s[C_];
    for (int i = tid; i < C_ * D_; i += 256) tile[i] = 0.0f;
    if (tid < C_) asum_s[tid] = 0.0f;
    __syncthreads();

#pragma unroll
    for (int c = 0; c < C_; c++)
#pragma unroll
        for (int k = 0; k < 8; k++)
            atomicAdd(&tile[c * D_ + lane + 32 * k], acc[c][k]);
    if (lane == 0) {
#pragma unroll
        for (int c = 0; c < C_; c++) atomicAdd(&asum_s[c], asum[c]);
    }
    __syncthreads();

    // ---- apply -a_sum * centers correction, push to global ----
    float* ob = out + b * C_ * D_;
    for (int i = tid; i < C_ * D_; i += 256) {
        const int c = i >> 8;  // i / D_
        const float v = tile[i] - asum_s[c] * centers[i];
        atomicAdd(&ob[i], v);
    }
}

extern "C" void kernel_launch(void* const* d_in, const int* in_sizes, int n_in,
                              void* d_out, int out_size) {
    const float* x       = (const float*)d_in[0];
    const float* centers = (const float*)d_in[1];
    const float* scale   = (const float*)d_in[2];
    float* out           = (float*)d_out;
    (void)in_sizes; (void)n_in;

    lde_zero_kernel<<<(out_size + 255) / 256, 256>>>(out, out_size);
    lde_main_kernel<<<NBLOCKS, 256>>>(x, centers, scale, out);
}

// round 2
// speedup vs baseline: 1.3692x; 1.3692x over previous
#include <cuda_runtime.h>
#include <cstdint>

#define B_ 16
#define T_ 2048
#define D_ 256
#define C_ 8
#define TCHUNK 64
#define NCHUNKS (T_ / TCHUNK)   // 32
#define NBLOCKS (B_ * NCHUNKS)  // 512
#define NSTAGE 4
#define SROWS 8                 // rows per stage (one per warp)
#define NSTAGES_ITER (TCHUNK / SROWS)  // 8

typedef unsigned long long ull;

__device__ __forceinline__ ull ffma2(ull a, ull b, ull c) {
    ull d;
    asm("fma.rn.f32x2 %0, %1, %2, %3;" : "=l"(d) : "l"(a), "l"(b), "l"(c));
    return d;
}
__device__ __forceinline__ float2 upk(ull v) {
    float2 r;
    asm("mov.b64 {%0, %1}, %2;" : "=f"(r.x), "=f"(r.y) : "l"(v));
    return r;
}
__device__ __forceinline__ ull pk2(float lo, float hi) {
    ull r;
    asm("mov.b64 %0, {%1, %2};" : "=l"(r) : "f"(lo), "f"(hi));
    return r;
}
__device__ __forceinline__ void lds_v2u64(ull& a, ull& b, uint32_t addr) {
    asm volatile("ld.shared.v2.b64 {%0, %1}, [%2];" : "=l"(a), "=l"(b) : "r"(addr));
}
__device__ __forceinline__ void cp16(uint32_t saddr, const void* g) {
    asm volatile("cp.async.cg.shared.global [%0], [%1], 16;" :: "r"(saddr), "l"(g));
}
#define CP_COMMIT() asm volatile("cp.async.commit_group;")
#define CP_WAIT(n)  asm volatile("cp.async.wait_group %0;" :: "n"(n))

__global__ void lde_zero_kernel(float* __restrict__ out, int n) {
    int i = blockIdx.x * blockDim.x + threadIdx.x;
    if (i < n) out[i] = 0.0f;
}

__global__ void __launch_bounds__(256, 2) lde_main_kernel(
    const float* __restrict__ x,        // (B,T,D)
    const float* __restrict__ centers,  // (C,D)
    const float* __restrict__ scale,    // (C,)
    float* __restrict__ out)            // (B, C*D)
{
    __shared__ float4 xstage[NSTAGE * SROWS * 64];  // 32 KB, aliased as scratch in epilogue
    __shared__ float4 c_sm4[C_ * 64];               // 8 KB centers
    __shared__ float  csq_s[C_];
    __shared__ float  scl_s[C_];
    __shared__ float  asum_s[C_];

    const int tid   = threadIdx.x;
    const int warp  = tid >> 5;
    const int lane  = tid & 31;
    const int b     = blockIdx.x / NCHUNKS;
    const int chunk = blockIdx.x % NCHUNKS;
    const int t0    = chunk * TCHUNK;

    const uint32_t xs_base = (uint32_t)__cvta_generic_to_shared(xstage);
    const uint32_t cs_base = (uint32_t)__cvta_generic_to_shared(c_sm4);

    const float4* gx4 = (const float4*)(x + ((size_t)b * T_ + t0) * D_);
    // gx4 for stage s starts at float4 index s*SROWS*64 (rows contiguous)

    // ---- kick off producer for stages 0..NSTAGE-2 ----
#pragma unroll
    for (int s = 0; s < NSTAGE - 1; s++) {
        const float4* src = gx4 + s * (SROWS * 64);
        uint32_t dst = xs_base + (s & (NSTAGE - 1)) * (SROWS * 64 * 16);
#pragma unroll
        for (int k = 0; k < 2; k++) {
            int idx = tid + k * 256;
            cp16(dst + idx * 16, src + idx);
        }
        CP_COMMIT();
    }

    // ---- centers into smem (overlaps with cp.async flight) ----
    for (int i = tid; i < C_ * 64; i += 256)
        c_sm4[i] = ((const float4*)centers)[i];
    if (tid < C_) { scl_s[tid] = scale[tid]; asum_s[tid] = 0.0f; }
    __syncthreads();

    // ---- ||c||^2, warp w handles cluster w ----
    {
        float4 u = c_sm4[warp * 64 + lane];
        float4 v = c_sm4[warp * 64 + 32 + lane];
        float s = u.x*u.x + u.y*u.y + u.z*u.z + u.w*u.w
                + v.x*v.x + v.y*v.y + v.z*v.z + v.w*v.w;
#pragma unroll
        for (int off = 16; off > 0; off >>= 1)
            s += __shfl_xor_sync(0xffffffffu, s, off);
        if (lane == 0) csq_s[warp] = s;
    }
    __syncthreads();

    float csq[C_], scl[C_];
#pragma unroll
    for (int c = 0; c < C_; c++) { csq[c] = csq_s[c]; scl[c] = scl_s[c]; }

    ull acc2[C_][4];
    float asum[C_];
#pragma unroll
    for (int c = 0; c < C_; c++) {
        asum[c] = 0.0f;
#pragma unroll
        for (int j = 0; j < 4; j++) acc2[c][j] = 0ULL;
    }

    // ---- main pipeline: 8 stages, 1 token per warp per stage ----
    for (int s = 0; s < NSTAGES_ITER; s++) {
        if (s + NSTAGE - 1 < NSTAGES_ITER) {
            int sp = s + NSTAGE - 1;
            const float4* src = gx4 + sp * (SROWS * 64);
            uint32_t dst = xs_base + (sp & (NSTAGE - 1)) * (SROWS * 64 * 16);
#pragma unroll
            for (int k = 0; k < 2; k++) {
                int idx = tid + k * 256;
                cp16(dst + idx * 16, src + idx);
            }
        }
        CP_COMMIT();
        CP_WAIT(3);
        __syncthreads();

        // compute token t0 + s*8 + warp from smem
        uint32_t xaddr = xs_base + ((s & (NSTAGE - 1)) * SROWS + warp) * 1024 + lane * 16;
        ull x0, x1, x2, x3;
        lds_v2u64(x0, x1, xaddr);
        lds_v2u64(x2, x3, xaddr + 512);

        float red[C_ + 1];
#pragma unroll
        for (int c = 0; c < C_; c++) {
            uint32_t caddr = cs_base + c * 1024 + lane * 16;
            ull c0, c1, c2, c3;
            lds_v2u64(c0, c1, caddr);
            lds_v2u64(c2, c3, caddr + 512);
            ull p = ffma2(x0, c0, ffma2(x1, c1, ffma2(x2, c2, ffma2(x3, c3, 0ULL))));
            float2 t = upk(p);
            red[c] = t.x + t.y;
        }
        {
            ull q = ffma2(x0, x0, ffma2(x1, x1, ffma2(x2, x2, ffma2(x3, x3, 0ULL))));
            float2 t = upk(q);
            red[C_] = t.x + t.y;
        }

#pragma unroll
        for (int off = 16; off > 0; off >>= 1) {
#pragma unroll
            for (int j = 0; j < C_ + 1; j++)
                red[j] += __shfl_xor_sync(0xffffffffu, red[j], off);
        }

        // logits = -scale_c*(||x||^2 - 2 x.c + ||c||^2) = scale_c*(2 x.c - ||x||^2 - ||c||^2)
        float lg[C_];
        float m = -1e30f;
#pragma unroll
        for (int c = 0; c < C_; c++) {
            lg[c] = scl[c] * (2.0f * red[c] - red[C_] - csq[c]);
            m = fmaxf(m, lg[c]);
        }
        float e[C_];
        float es = 0.0f;
#pragma unroll
        for (int c = 0; c < C_; c++) { e[c] = __expf(lg[c] - m); es += e[c]; }
        const float inv = 1.0f / es;

#pragma unroll
        for (int c = 0; c < C_; c++) {
            const float a = e[c] * inv;
            asum[c] += a;
            const ull a2 = pk2(a, a);
            acc2[c][0] = ffma2(a2, x0, acc2[c][0]);
            acc2[c][1] = ffma2(a2, x1, acc2[c][1]);
            acc2[c][2] = ffma2(a2, x2, acc2[c][2]);
            acc2[c][3] = ffma2(a2, x3, acc2[c][3]);
        }
        __syncthreads();   // stage buffer may be overwritten next iteration
    }

    // ---- a_sum to smem (values identical across lanes) ----
    if (lane == 0) {
#pragma unroll
        for (int c = 0; c < C_; c++) atomicAdd(&asum_s[c], asum[c]);
    }
    __syncthreads();

    // ---- block tree reduction in the (now free) stage buffer, conflict-free STS.128 ----
    float* scr = (float*)xstage;            // 8192 floats
    float4* scr4 = (float4*)xstage;

    if (warp < 4) {
        float* dst = scr + warp * 2048;
#pragma unroll
        for (int c = 0; c < C_; c++) {
            float2 p0 = upk(acc2[c][0]), p1 = upk(acc2[c][1]);
            float2 p2 = upk(acc2[c][2]), p3 = upk(acc2[c][3]);
            *(float4*)(dst + c * 256 + 4 * lane)       = make_float4(p0.x, p0.y, p1.x, p1.y);
            *(float4*)(dst + c * 256 + 128 + 4 * lane) = make_float4(p2.x, p2.y, p3.x, p3.y);
        }
    }
    __syncthreads();
    if (warp >= 4) {
        float* dst = scr + (warp - 4) * 2048;
#pragma unroll
        for (int c = 0; c < C_; c++) {
            float2 p0 = upk(acc2[c][0]), p1 = upk(acc2[c][1]);
            float2 p2 = upk(acc2[c][2]), p3 = upk(acc2[c][3]);
            float4* d0 = (float4*)(dst + c * 256 + 4 * lane);
            float4* d1 = (float4*)(dst + c * 256 + 128 + 4 * lane);
            float4 t0v = *d0, t1v = *d1;
            t0v.x += p0.x; t0v.y += p0.y; t0v.z += p1.x; t0v.w += p1.y;
            t1v.x += p2.x; t1v.y += p2.y; t1v.z += p3.x; t1v.w += p3.y;
            *d0 = t0v; *d1 = t1v;
        }
    }
    __syncthreads();
    for (int i = tid; i < 1024; i += 256) {
        float4 a = scr4[i], b4 = scr4[i + 1024];
        a.x += b4.x; a.y += b4.y; a.z += b4.z; a.w += b4.w;
        scr4[i] = a;
    }
    __syncthreads();
    for (int i = tid; i < 512; i += 256) {
        float4 a = scr4[i], b4 = scr4[i + 512];
        a.x += b4.x; a.y += b4.y; a.z += b4.z; a.w += b4.w;
        scr4[i] = a;
    }
    __syncthreads();

    // ---- global accumulate with -a_sum * centers correction ----
    const float* cflat = (const float*)c_sm4;
    float* ob = out + b * (C_ * D_);
    for (int i = tid; i < C_ * D_; i += 256) {
        const int c = i >> 8;
        atomicAdd(&ob[i], scr[i] - asum_s[c] * cflat[i]);
    }
}

extern "C" void kernel_launch(void* const* d_in, const int* in_sizes, int n_in,
                              void* d_out, int out_size) {
    const float* x       = (const float*)d_in[0];
    const float* centers = (const float*)d_in[1];
    const float* scale   = (const float*)d_in[2];
    float* out           = (float*)d_out;
    (void)in_sizes; (void)n_in;

    lde_zero_kernel<<<(out_size + 255) / 256, 256>>>(out, out_size);
    lde_main_kernel<<<NBLOCKS, 256>>>(x, centers, scale, out);
}

// round 3
// speedup vs baseline: 1.6655x; 1.2164x over previous
#include <cuda_runtime.h>
#include <cstdint>

#define B_ 16
#define T_ 2048
#define D_ 256
#define C_ 8
#define TCHUNK 128
#define TILE 32
#define NTILES (TCHUNK / TILE)    // 4
#define NSTAGE 3
#define NCHUNKS (T_ / TCHUNK)     // 16
#define NBLOCKS (B_ * NCHUNKS)    // 256

// shared memory layout (float offsets)
#define OFF_CT   24576            // after XBUF: 3*32*64 float4 = 24576 floats
#define OFF_LOG  26624            // 32*9 = 288 floats
#define OFF_AS   26912            // 32*8 = 256 floats
#define OFF_ASUM 27168            // 8
#define OFF_CSQ  27176            // 8
#define OFF_SCL  27184            // 8
#define SMEM_FLOATS 27200
#define SMEM_BYTES (SMEM_FLOATS * 4)

typedef unsigned long long ull;

union f4u { float4 v; ull u[2]; };

__device__ __forceinline__ ull ffma2(ull a, ull b, ull c) {
    ull d;
    asm("fma.rn.f32x2 %0, %1, %2, %3;" : "=l"(d) : "l"(a), "l"(b), "l"(c));
    return d;
}
__device__ __forceinline__ float2 upk(ull v) {
    float2 r;
    asm("mov.b64 {%0, %1}, %2;" : "=f"(r.x), "=f"(r.y) : "l"(v));
    return r;
}
__device__ __forceinline__ void cp16(uint32_t saddr, const void* g) {
    asm volatile("cp.async.cg.shared.global [%0], [%1], 16;" :: "r"(saddr), "l"(g));
}
#define CP_COMMIT() asm volatile("cp.async.commit_group;")
#define CP_WAIT(n)  asm volatile("cp.async.wait_group %0;" :: "n"(n))

__global__ void lde_zero_kernel(float* __restrict__ out, int n) {
    int i = blockIdx.x * blockDim.x + threadIdx.x;
    if (i < n) out[i] = 0.0f;
}

__global__ void __launch_bounds__(256, 2) lde_main_kernel(
    const float* __restrict__ x,        // (B,T,D)
    const float* __restrict__ centers,  // (C,D)
    const float* __restrict__ scale,    // (C,)
    float* __restrict__ out)            // (B, C*D)
{
    extern __shared__ float smem_f[];
    float4* xbuf   = (float4*)smem_f;               // [NSTAGE][TILE][64], swizzled
    float4* ct     = (float4*)(smem_f + OFF_CT);    // [64 d4][8 c]
    float*  logit  = smem_f + OFF_LOG;              // [32 t][9] (8 dots + xsq)
    float*  a_s    = smem_f + OFF_AS;               // [32 t][8 c]
    float*  asum_s = smem_f + OFF_ASUM;
    float*  csq_s  = smem_f + OFF_CSQ;
    float*  scl_s  = smem_f + OFF_SCL;

    const int tid  = threadIdx.x;
    const int w    = tid >> 5;
    const int lane = tid & 31;
    const int b     = blockIdx.x / NCHUNKS;
    const int chunk = blockIdx.x % NCHUNKS;

    const float4* gx4 = (const float4*)(x + ((size_t)b * T_ + chunk * TCHUNK) * D_);
    const uint32_t xs_base = (uint32_t)__cvta_generic_to_shared(xbuf);

    // ---- prefetch first NSTAGE tiles (swizzled: slot = d4 ^ t) ----
#pragma unroll
    for (int s = 0; s < NSTAGE; s++) {
        const float4* src = gx4 + s * (TILE * 64);
#pragma unroll
        for (int j = 0; j < 8; j++) {
            int i = tid + j * 256;            // 0..2047
            int t = i >> 6, d4 = i & 63;
            uint32_t dst = xs_base + (uint32_t)((s * 2048 + t * 64 + (d4 ^ t)) * 16);
            cp16(dst, src + i);
        }
        CP_COMMIT();
    }

    // ---- init smem (overlaps cp.async flight) ----
    for (int i = tid; i < 288; i += 256) logit[i] = 0.0f;
    if (tid < C_) { asum_s[tid] = 0.0f; scl_s[tid] = scale[tid]; }
    for (int i = tid; i < C_ * D_; i += 256) {
        int c = i >> 8, d = i & 255;
        ((float*)ct)[((d >> 2) * 8 + c) * 4 + (d & 3)] = centers[i];
    }
    // csq: warp w handles cluster w
    {
        float s = 0.0f;
        for (int d = lane; d < D_; d += 32) {
            float v = centers[w * D_ + d];
            s = fmaf(v, v, s);
        }
#pragma unroll
        for (int o = 16; o; o >>= 1) s += __shfl_xor_sync(0xffffffffu, s, o);
        if (lane == 0) csq_s[w] = s;
    }
    __syncthreads();

    float acc[C_];
#pragma unroll
    for (int c = 0; c < C_; c++) acc[c] = 0.0f;
    const int d4l  = w * 8 + (lane >> 2);   // float4 slot index this lane owns (phase B)
    const int comp = lane & 3;

    for (int k = 0; k < NTILES; k++) {
        CP_WAIT(2);
        __syncthreads();
        const float4* xb = xbuf + (k % NSTAGE) * 2048;

        // ---- phase A: lane = token, warp w covers d4 in [8w, 8w+8) ----
        {
            ull red[9];
#pragma unroll
            for (int j = 0; j < 9; j++) red[j] = 0ULL;
#pragma unroll
            for (int i = 0; i < 8; i++) {
                const int d4 = w * 8 + i;
                f4u xv; xv.v = xb[lane * 64 + (d4 ^ lane)];
#pragma unroll
                for (int c = 0; c < C_; c++) {
                    f4u cv; cv.v = ct[d4 * 8 + c];
                    red[c] = ffma2(xv.u[0], cv.u[0], ffma2(xv.u[1], cv.u[1], red[c]));
                }
                red[8] = ffma2(xv.u[0], xv.u[0], ffma2(xv.u[1], xv.u[1], red[8]));
            }
#pragma unroll
            for (int j = 0; j < 9; j++) {
                float2 p = upk(red[j]);
                atomicAdd(&logit[lane * 9 + j], p.x + p.y);
            }
        }
        __syncthreads();

        // ---- softmax: thread (t = tid/8, c = tid%8) ----
        {
            const int t = tid >> 3, c = tid & 7;
            const float dot = logit[t * 9 + c];
            const float xsq = logit[t * 9 + 8];
            float lg = scl_s[c] * (2.0f * dot - xsq - csq_s[c]);
            float m = lg;
            m = fmaxf(m, __shfl_xor_sync(0xffffffffu, m, 1));
            m = fmaxf(m, __shfl_xor_sync(0xffffffffu, m, 2));
            m = fmaxf(m, __shfl_xor_sync(0xffffffffu, m, 4));
            const float e = __expf(lg - m);
            float sd = e;
            sd += __shfl_xor_sync(0xffffffffu, sd, 1);
            sd += __shfl_xor_sync(0xffffffffu, sd, 2);
            sd += __shfl_xor_sync(0xffffffffu, sd, 4);
            const float a = e / sd;
            a_s[t * 8 + c] = a;
            float r = a;
            r += __shfl_xor_sync(0xffffffffu, r, 8);
            r += __shfl_xor_sync(0xffffffffu, r, 16);
            if (lane < 8) atomicAdd(&asum_s[lane], r);
        }
        __syncthreads();

        // ---- phase B: lane = dim (dim = 32w + lane), loop tokens ----
        for (int i = tid; i < 288; i += 256) logit[i] = 0.0f;  // reset for next tile
        {
            const float* xbf = (const float*)xb;
#pragma unroll 4
            for (int t = 0; t < TILE; t++) {
                const float xval = xbf[(t * 64 + (d4l ^ t)) * 4 + comp];
                const float4 a0 = *(const float4*)&a_s[t * 8];
                const float4 a1 = *(const float4*)&a_s[t * 8 + 4];
                acc[0] = fmaf(a0.x, xval, acc[0]);
                acc[1] = fmaf(a0.y, xval, acc[1]);
                acc[2] = fmaf(a0.z, xval, acc[2]);
                acc[3] = fmaf(a0.w, xval, acc[3]);
                acc[4] = fmaf(a1.x, xval, acc[4]);
                acc[5] = fmaf(a1.y, xval, acc[5]);
                acc[6] = fmaf(a1.z, xval, acc[6]);
                acc[7] = fmaf(a1.w, xval, acc[7]);
            }
        }
        __syncthreads();

        // ---- prefetch tile k+NSTAGE into the buffer just freed ----
        if (k + NSTAGE < NTILES) {
            const int s = k + NSTAGE;
            const float4* src = gx4 + s * (TILE * 64);
#pragma unroll
            for (int j = 0; j < 8; j++) {
                int i = tid + j * 256;
                int t = i >> 6, d4 = i & 63;
                uint32_t dst = xs_base +
                    (uint32_t)(((s % NSTAGE) * 2048 + t * 64 + (d4 ^ t)) * 16);
                cp16(dst, src + i);
            }
        }
        CP_COMMIT();
    }

    // ---- epilogue: lane owns dim = 32w + lane for all 8 clusters ----
    const int dim = w * 32 + lane;
    float* ob = out + b * (C_ * D_) + dim;
#pragma unroll
    for (int c = 0; c < C_; c++) {
        const float cv = ((const float*)ct)[(d4l * 8 + c) * 4 + comp]; // centers[c][dim]
        atomicAdd(ob + c * 256, acc[c] - asum_s[c] * cv);
    }
}

extern "C" void kernel_launch(void* const* d_in, const int* in_sizes, int n_in,
                              void* d_out, int out_size) {
    const float* x       = (const float*)d_in[0];
    const float* centers = (const float*)d_in[1];
    const float* scale   = (const float*)d_in[2];
    float* out           = (float*)d_out;
    (void)in_sizes; (void)n_in;

    cudaFuncSetAttribute(lde_main_kernel,
                         cudaFuncAttributeMaxDynamicSharedMemorySize, SMEM_BYTES);

    lde_zero_kernel<<<(out_size + 255) / 256, 256>>>(out, out_size);
    lde_main_kernel<<<NBLOCKS, 256, SMEM_BYTES>>>(x, centers, scale, out);
}